// round 14
// baseline (speedup 1.0000x reference)
#include <cuda_runtime.h>
#include <cuda_fp16.h>
#include <math.h>

#define H 4096

// Finals (36H) + split-tile partials. fp16 weight copies as device globals.
__device__ float g_scratch[47 * H];
__device__ int g_tick[320];               // per-tile tickets, self-resetting
__device__ __half g_L16[3 * H * H];       // 96MB fp16 copy of L l=0..2
__device__ __half g_R16[3 * H * H];       // 96MB fp16 copy of R l=0..2

struct P {
    const float* L; const float* R;
    const float* x; const float* hp;
    const float* b; const float* Wsc;
    float* xL; float* hL; float* hR;          // hR: l=0..1 only
    float* Rr; float* Rz1;
    float* Rrh; float* RoneMZ; float* Rz2h;
    float* Lht; float* Lzh;
    float* r; float* z1; float* rh; float* oneMZ; float* z2h;
    float* htilde; float* zhtil;
    float* part;
    __half* L16; __half* R16;
    float* out;
};

// ---------------- helpers ----------------
__device__ __forceinline__ float4 f4add(float4 a, float4 b) {
    return make_float4(a.x + b.x, a.y + b.y, a.z + b.z, a.w + b.w);
}
__device__ __forceinline__ float4 f4fma(float4 a, float4 b, float4 c) {
    return make_float4(a.x * b.x + c.x, a.y * b.y + c.y, a.z * b.z + c.z, a.w * b.w + c.w);
}
__device__ __forceinline__ float4 f4smad(float s, float4 a, float4 acc) {
    return make_float4(s * a.x + acc.x, s * a.y + acc.y, s * a.z + acc.z, s * a.w + acc.w);
}
__device__ __forceinline__ float4 f4rsub1(float4 a) {
    return make_float4(1.f - a.x, 1.f - a.y, 1.f - a.z, 1.f - a.w);
}
__device__ __forceinline__ float ftanh(float x) { return 1.f - 2.f / (1.f + __expf(2.f * x)); }
__device__ __forceinline__ float fsig(float x)  { return 1.f / (1.f + __expf(-x)); }
__device__ __forceinline__ float4 f4tanh(float4 a) {
    return make_float4(ftanh(a.x), ftanh(a.y), ftanh(a.z), ftanh(a.w));
}
__device__ __forceinline__ float4 f4sig(float4 a) {
    return make_float4(fsig(a.x), fsig(a.y), fsig(a.z), fsig(a.w));
}
__device__ __forceinline__ float dot4(float4 a, float4 b) {
    return a.x * b.x + a.y * b.y + a.z * b.z + a.w * b.w;
}
__device__ __forceinline__ float4 ld4(const float* p, int i) {
    return __ldg(((const float4*)p) + i);
}
__device__ __forceinline__ float wred(float v) {
    v += __shfl_down_sync(0xffffffffu, v, 16);
    v += __shfl_down_sync(0xffffffffu, v, 8);
    v += __shfl_down_sync(0xffffffffu, v, 4);
    v += __shfl_down_sync(0xffffffffu, v, 2);
    v += __shfl_down_sync(0xffffffffu, v, 1);
    return v;
}

// Candidate values for the score_mix fused into stage MODE (2,3,4).
template<int MODE>
__device__ __forceinline__ void cands(const P& p, int idx, int l, float4* cc) {
    float4 b_ = ld4(p.b + l * H, idx);
    if (MODE == 2) {
        if (l < 3) {
            float4 hl = ld4(p.hL + l * H, idx);
            float4 rr = ld4(p.Rr + l * H, idx);
            float4 rz = ld4(p.Rz1 + l * H, idx);
            cc[0] = f4fma(hl, rr, b_);
            cc[1] = f4rsub1(f4add(rz, b_));
            cc[2] = f4fma(hl, rz, b_);
        } else {
            float4 hp4 = ld4(p.hp, idx);
            float4 r4  = ld4(p.r, idx);
            float4 z4  = ld4(p.z1, idx);
            cc[0] = f4fma(hp4, r4, b_);
            cc[1] = f4rsub1(f4add(z4, b_));
            cc[2] = f4fma(hp4, z4, b_);
        }
    } else if (MODE == 3) {
        if (l < 3)
            cc[0] = f4tanh(f4add(f4add(ld4(p.xL + l * H, idx), ld4(p.Rrh + l * H, idx)), b_));
        else
            cc[0] = f4tanh(f4add(f4add(ld4(p.x, idx), ld4(p.rh, idx)), b_));
    } else {  // MODE == 4
        if (l < 3)
            cc[0] = f4fma(ld4(p.Lht + l * H, idx), ld4(p.RoneMZ + l * H, idx), b_);
        else
            cc[0] = f4fma(ld4(p.htilde, idx), ld4(p.oneMZ, idx), b_);
    }
}

// fp32 streaming matvec (R4/R10-proven pattern). Streaming (.cs) weight reads.
template<int NVST, int RPT>
__device__ __forceinline__ void run_mv(const float* __restrict__ Wp,
                                       const float* v0s, const float* v1s, const float* v2s,
                                       int nv, float4& a0, float4& a1, float4& a2) {
    float4 x0 = make_float4(0.f, 0.f, 0.f, 0.f), x1 = x0, x2 = x0;
    if (NVST == 1 || nv == 1) {
        #pragma unroll 8
        for (int h = 0; h < RPT; ++h) {
            float4 w = __ldcs((const float4*)(Wp + (size_t)h * H));
            x0 = f4smad(v0s[h], w, x0);
        }
    } else if (nv == 2) {
        #pragma unroll 4
        for (int h = 0; h < RPT; ++h) {
            float4 w = __ldcs((const float4*)(Wp + (size_t)h * H));
            float s0 = v0s[h], s1 = v1s[h];
            x0 = f4smad(s0, w, x0);
            x1 = f4smad(s1, w, x1);
        }
    } else {
        #pragma unroll 4
        for (int h = 0; h < RPT; ++h) {
            float4 w = __ldcs((const float4*)(Wp + (size_t)h * H));
            float s0 = v0s[h], s1 = v1s[h], s2 = v2s[h];
            x0 = f4smad(s0, w, x0);
            x1 = f4smad(s1, w, x1);
            x2 = f4smad(s2, w, x2);
        }
    }
    a0 = x0; a1 = x1; a2 = x2;
}

// fp32 matvec (nv=2) + on-the-fly fp16 conversion store. .cs reads so the
// fp16 writes stay L2-resident for the next stage.
template<int RPT>
__device__ __forceinline__ void run_mv_conv(const float* __restrict__ Wp, __half* O16,
                                            const float* v0s, const float* v1s,
                                            float4& a0, float4& a1) {
    float4 x0 = make_float4(0.f, 0.f, 0.f, 0.f), x1 = x0;
    #pragma unroll 4
    for (int h = 0; h < RPT; ++h) {
        float4 w = __ldcs((const float4*)(Wp + (size_t)h * H));
        __half2 h01 = __floats2half2_rn(w.x, w.y);
        __half2 h23 = __floats2half2_rn(w.z, w.w);
        uint2 u;
        u.x = *reinterpret_cast<unsigned*>(&h01);
        u.y = *reinterpret_cast<unsigned*>(&h23);
        *reinterpret_cast<uint2*>(O16 + (size_t)h * H) = u;
        float s0 = v0s[h], s1 = v1s[h];
        x0 = f4smad(s0, w, x0);
        x1 = f4smad(s1, w, x1);
    }
    a0 = x0; a1 = x1;
}

// fp16-weight streaming matvec: 16B loads, MANUAL SOFTWARE PIPELINE so PF
// LDG.128s stay in flight regardless of ptxas scheduling. CS: evict-first.
template<int NVST, int RPT, bool CS>
__device__ __forceinline__ void run_mv_f16w(const __half* __restrict__ Wp,
                                            const float* v0s, const float* v1s, const float* v2s,
                                            int nv, float a[NVST][8]) {
    constexpr int PF = (NVST == 1) ? 4 : 2;
    #pragma unroll
    for (int j = 0; j < NVST; ++j)
        #pragma unroll
        for (int f = 0; f < 8; ++f) a[j][f] = 0.f;

    uint4 buf[PF];
    #pragma unroll
    for (int i = 0; i < PF; ++i)
        buf[i] = CS ? __ldcs((const uint4*)(Wp + (size_t)i * H))
                    : __ldg((const uint4*)(Wp + (size_t)i * H));

    for (int h0 = 0; h0 < RPT; h0 += PF) {
        uint4 nxt[PF];
        #pragma unroll
        for (int i = 0; i < PF; ++i) {
            int hn = h0 + PF + i;
            hn = (hn < RPT) ? hn : 0;          // clamped dummy re-read at tail
            nxt[i] = CS ? __ldcs((const uint4*)(Wp + (size_t)hn * H))
                        : __ldg((const uint4*)(Wp + (size_t)hn * H));
        }
        #pragma unroll
        for (int i = 0; i < PF; ++i) {
            const int h = h0 + i;
            uint4 raw = buf[i];
            float2 f0 = __half22float2(*reinterpret_cast<__half2*>(&raw.x));
            float2 f1 = __half22float2(*reinterpret_cast<__half2*>(&raw.y));
            float2 f2 = __half22float2(*reinterpret_cast<__half2*>(&raw.z));
            float2 f3 = __half22float2(*reinterpret_cast<__half2*>(&raw.w));
            float wv[8] = {f0.x, f0.y, f1.x, f1.y, f2.x, f2.y, f3.x, f3.y};
            float s0 = v0s[h];
            #pragma unroll
            for (int f = 0; f < 8; ++f) a[0][f] += s0 * wv[f];
            if (NVST > 1 && nv > 1) {
                float s1 = v1s[h];
                #pragma unroll
                for (int f = 0; f < 8; ++f) a[1][f] += s1 * wv[f];
            }
            if (NVST > 2 && nv > 2) {
                float s2 = v2s[h];
                #pragma unroll
                for (int f = 0; f < 8; ++f) a[2][f] += s2 * wv[f];
            }
        }
        #pragma unroll
        for (int i = 0; i < PF; ++i) buf[i] = nxt[i];
    }
}

// ---------------------------------------------------------------------------
// Fused kernel (R13 structure): [prologue -> vsm] + static pair-aware split
// streaming matvec. A converts L->fp16; B converts R->fp16 (.cs reads keep
// R16 L2-resident); C streams R16 (.cs, L2 hits); D streams L16 (default,
// repopulates L2); E streams L16 (.cs, hits D's lines).
// ---------------------------------------------------------------------------
template<int MODE>
__global__ void __launch_bounds__(512, 2) fused_kernel(P p) {
    extern __shared__ float vsm[];                 // [NVST][H] input vectors
    constexpr int NVST = (MODE == 2) ? 3 : ((MODE == 3 || MODE == 4) ? 1 : 2);
    __shared__ float4 smred[2][32][16];            // fp32 modes (NVST<=2 there)
    __shared__ float sm16[16][8][NVST * 8];        // fp16 modes
    __shared__ float red[12][16];
    __shared__ float wsm[3][4];
    __shared__ int sold;

    const int tx = threadIdx.x, ty = threadIdx.y;  // 16 x 32
    const int t = ty * 16 + tx;
    const int lane = t & 31, warp = t >> 5;
    const int bx = blockIdx.x;

    // ---------------- prologue: fill vsm ----------------
    if (MODE == 0) {
        #pragma unroll
        for (int c = 0; c < 2; ++c) {
            int idx = t + c * 512;
            ((float4*)vsm)[idx]       = ld4(p.x, idx);
            ((float4*)(vsm + H))[idx] = ld4(p.hp, idx);
        }
        __syncthreads();
    } else if (MODE == 1) {
        #pragma unroll
        for (int c = 0; c < 2; ++c) {
            int idx = t + c * 512;
            float4 z14 = f4sig(f4add(f4add(ld4(p.xL, idx),     ld4(p.hR, idx)),     ld4(p.b, idx)));
            float4 r4  = f4sig(f4add(f4add(ld4(p.xL + H, idx), ld4(p.hR + H, idx)), ld4(p.b + H, idx)));
            ((float4*)vsm)[idx]       = r4;    // v0 = r
            ((float4*)(vsm + H))[idx] = z14;   // v1 = z1
            if (bx == 0) {
                ((float4*)p.r)[idx]  = r4;
                ((float4*)p.z1)[idx] = z14;
            }
        }
        if (bx == 0 && t < 3) p.out[4096 + t] = (t == 1) ? 1.f : 0.f;
        __syncthreads();
    } else {
        constexpr int NM = (MODE == 2) ? 3 : 1;
        float s[NM * 4];
        #pragma unroll
        for (int d = 0; d < NM * 4; ++d) s[d] = 0.f;

        #pragma unroll
        for (int c = 0; c < 2; ++c) {
            int idx = t + c * 512;
            float4 ws = ld4(p.Wsc, idx);
            #pragma unroll
            for (int ll = 0; ll < 4; ++ll) {
                float4 cc[NM];
                cands<MODE>(p, idx, ll, cc);
                #pragma unroll
                for (int m = 0; m < NM; ++m) s[m * 4 + ll] += dot4(cc[m], ws);
            }
        }
        #pragma unroll
        for (int d = 0; d < NM * 4; ++d) {
            float v = wred(s[d]);
            if (lane == 0) red[d][warp] = v;
        }
        __syncthreads();
        if (t == 0) {
            #pragma unroll
            for (int m = 0; m < NM; ++m) {
                float sc[4];
                #pragma unroll
                for (int l2 = 0; l2 < 4; ++l2) {
                    float a = 0.f;
                    #pragma unroll
                    for (int w2 = 0; w2 < 16; ++w2) a += red[m * 4 + l2][w2];
                    sc[l2] = a;
                }
                int amax = 0; float m1 = sc[0];
                for (int l2 = 1; l2 < 4; ++l2) if (sc[l2] > m1) { m1 = sc[l2]; amax = l2; }
                float m2 = -INFINITY;
                for (int l2 = 0; l2 < 4; ++l2) if (l2 != amax && sc[l2] > m2) m2 = sc[l2];
                float e[4], se = 0.f;
                for (int l2 = 0; l2 < 4; ++l2) { e[l2] = __expf(sc[l2] - m1); se += e[l2]; }
                for (int l2 = 0; l2 < 4; ++l2) wsm[m][l2] = e[l2] / se;
                if (bx == 0) {
                    int slot = (MODE == 2) ? (m * 2) : ((MODE == 3) ? 1 : 3);
                    p.out[4096 + 3 + slot] = (float)amax;
                    p.out[4096 + 9 + slot] = m1 - m2;
                }
            }
        }
        __syncthreads();

        float* gv[NM];
        if (MODE == 2) { gv[0] = p.rh; gv[1] = p.oneMZ; gv[2] = p.z2h; }
        if (MODE == 3) { gv[0] = p.htilde; }
        if (MODE == 4) { gv[0] = p.zhtil; }
        #pragma unroll
        for (int c = 0; c < 2; ++c) {
            int idx = t + c * 512;
            float4 v[NM];
            #pragma unroll
            for (int m = 0; m < NM; ++m) v[m] = make_float4(0.f, 0.f, 0.f, 0.f);
            #pragma unroll
            for (int ll = 0; ll < 4; ++ll) {
                float4 cc[NM];
                cands<MODE>(p, idx, ll, cc);
                #pragma unroll
                for (int m = 0; m < NM; ++m) v[m] = f4smad(wsm[m][ll], cc[m], v[m]);
            }
            #pragma unroll
            for (int m = 0; m < NM; ++m) {
                ((float4*)(vsm + m * H))[idx] = v[m];
                if (bx == 0) ((float4*)gv[m])[idx] = v[m];
            }
        }
        __syncthreads();
    }

    // ---------------- decode (R10 static pair-aware split) ----------------
    for (int seg = 0; seg < 2; ++seg) {
        int tile, rowbase, half, contrib;
        if (seg == 0) {
            if (MODE == 0)            { tile = bx;        rowbase = 0;    half = 0; contrib = -1; }
            else if (bx < 104)        { tile = bx;        rowbase = 0;    half = 1; contrib = 0; }
            else if (bx < 192)        { tile = bx;        rowbase = 0;    half = 0; contrib = -1; }
            else                      { tile = bx - 192;  rowbase = 2048; half = 1; contrib = 1; }
        } else {
            if (MODE != 0 || bx >= 192) break;
            tile = 296 + (bx >> 3); rowbase = (bx & 7) * 512; half = 2; contrib = bx & 7;
        }

        const int unit = tile >> 6;
        const int kb = tile & 63;
        int l, nv;
        float *y0 = nullptr, *y1 = nullptr, *y2 = nullptr;
        const float *v0 = vsm, *v1 = vsm + H, *v2 = vsm + 2 * H;
        if (MODE == 0) {
            if (unit < 3) { l = unit;     nv = 2; y0 = p.xL; y1 = p.hL; }
            else          { l = unit - 3; nv = 1; y0 = p.hR; v0 = vsm + H; }
        } else {
            l = unit;
            nv = (MODE == 2) ? 3 : ((MODE == 1) ? 2 : 1);
            if (MODE == 1) { y0 = p.Rr;  y1 = p.Rz1; }
            if (MODE == 2) { y0 = p.Rrh; y1 = p.RoneMZ; y2 = p.Rz2h; }
            if (MODE == 3) { y0 = p.Lht; }
            if (MODE == 4) { y0 = p.Lzh; }
        }

        if (MODE >= 2) {
            // ---------- fp16 path: (8,64) indexing, 16B pipelined loads -----
            const int tx8 = t & 7, ty64 = t >> 3;
            const int k0 = (kb << 6) + (tx8 << 3);
            const int rpt = half ? 32 : 64;
            const int h0 = rowbase + ty64 * rpt;
            const __half* W16 = ((MODE == 2) ? p.R16 : p.L16)
                                + (size_t)l * H * H + (size_t)h0 * H + k0;
            constexpr bool CS = (MODE != 3);   // C & E evict-first; D populates L2
            float a[NVST][8];
            if (half) run_mv_f16w<NVST, 32, CS>(W16, v0 + h0, v1 + h0, v2 + h0, nv, a);
            else      run_mv_f16w<NVST, 64, CS>(W16, v0 + h0, v1 + h0, v2 + h0, nv, a);

            // intra-warp: combine the 4 ty-slices (lane>>3) per warp
            #pragma unroll
            for (int j = 0; j < NVST; ++j)
                #pragma unroll
                for (int f = 0; f < 8; ++f) {
                    float v = a[j][f];
                    v += __shfl_down_sync(0xffffffffu, v, 16);
                    v += __shfl_down_sync(0xffffffffu, v, 8);
                    a[j][f] = v;
                }
            if (lane < 8) {
                #pragma unroll
                for (int j = 0; j < NVST; ++j)
                    #pragma unroll
                    for (int f = 0; f < 8; ++f)
                        sm16[warp][lane][j * 8 + f] = a[j][f];
            }
            __syncthreads();

            // 16-way fixed-order tree + output
            const int nel = nv * 64;
            float accv = 0.f; int ej = 0, ec = 0;
            if (t < nel) {
                ej = t >> 6; ec = t & 63;
                const int txe = ec >> 3, fe = ec & 7;
                #pragma unroll
                for (int w2 = 0; w2 < 16; ++w2) accv += sm16[w2][txe][ej * 8 + fe];
            }
            if (contrib < 0) {
                if (t < nel) {
                    float* y = (ej == 0) ? y0 : ((ej == 1) ? y1 : y2);
                    y[l * H + (kb << 6) + ec] = accv;
                }
            } else {
                if (t < nel) {
                    p.part[(((contrib * 3 + ej) * 104 + tile) << 6) + ec] = accv;
                    __threadfence();
                }
                __syncthreads();
                if (t == 0) sold = atomicAdd(&g_tick[tile], 1);
                __syncthreads();
                if (sold == 1) {
                    __threadfence();
                    if (t < nel) {
                        float aa = __ldcg(p.part + (((0 * 3 + ej) * 104 + tile) << 6) + ec)
                                 + __ldcg(p.part + (((1 * 3 + ej) * 104 + tile) << 6) + ec);
                        float* y = (ej == 0) ? y0 : ((ej == 1) ? y1 : y2);
                        y[l * H + (kb << 6) + ec] = aa;
                    }
                    if (t == 0) g_tick[tile] = 0;
                }
            }
            __syncthreads();
            continue;
        }

        // ---------- fp32 path (MODE 0/1), R13 code ----------
        const int k0 = (kb << 6) + (tx << 2);
        const int rpt = (half == 0) ? 128 : ((half == 1) ? 64 : 16);
        const int h0 = rowbase + ty * rpt;
        float4 a0 = make_float4(0.f, 0.f, 0.f, 0.f), a1 = a0, a2 = a0;

        if (MODE == 0) {
            const float* W = (unit < 3) ? p.L : p.R;
            const float* Wp = W + (size_t)l * H * H + (size_t)h0 * H + k0;
            if (unit < 3) {
                __half* O16 = p.L16 + (size_t)l * H * H + (size_t)h0 * H + k0;
                run_mv_conv<128>(Wp, O16, v0 + h0, v1 + h0, a0, a1);
            } else if (half == 0) {
                run_mv<2, 128>(Wp, v0 + h0, v1 + h0, v2 + h0, 1, a0, a1, a2);
            } else {
                run_mv<2, 16>(Wp, v0 + h0, v1 + h0, v2 + h0, 1, a0, a1, a2);
            }
        } else {
            const float* Wp = p.R + (size_t)l * H * H + (size_t)h0 * H + k0;
            __half* O16 = p.R16 + (size_t)l * H * H + (size_t)h0 * H + k0;
            if (half == 0) run_mv_conv<128>(Wp, O16, v0 + h0, v1 + h0, a0, a1);
            else           run_mv_conv<64>(Wp, O16, v0 + h0, v1 + h0, a0, a1);
        }

        if (seg == 1) __syncthreads();
        smred[0][ty][tx] = a0;
        if (nv > 1) smred[1][ty][tx] = a1;
        __syncthreads();

        #pragma unroll
        for (int s = 16; s > 0; s >>= 1) {
            if (ty < s) {
                #pragma unroll
                for (int vv = 0; vv < 2; ++vv)
                    if (vv < nv)
                        smred[vv][ty][tx] = f4add(smred[vv][ty][tx], smred[vv][ty + s][tx]);
            }
            __syncthreads();
        }

        if (contrib < 0) {
            if (ty == 0) {
                *(float4*)(y0 + l * H + k0) = smred[0][0][tx];
                if (nv > 1) *(float4*)(y1 + l * H + k0) = smred[1][0][tx];
            }
        } else if (MODE != 0) {
            if (ty == 0) {
                #pragma unroll
                for (int j = 0; j < 2; ++j)
                    if (j < nv)
                        *(float4*)(p.part + (((contrib * 3 + j) * 104 + tile) << 6) + (tx << 2))
                            = smred[j][0][tx];
                __threadfence();
            }
            __syncthreads();
            if (t == 0) sold = atomicAdd(&g_tick[tile], 1);
            __syncthreads();
            if (sold == 1) {
                __threadfence();
                if (t < 64 * nv) {
                    const int j = t >> 6, c2 = t & 63;
                    float a = __ldcg(p.part + (((0 * 3 + j) * 104 + tile) << 6) + c2)
                            + __ldcg(p.part + (((1 * 3 + j) * 104 + tile) << 6) + c2);
                    float* y = (j == 0) ? y0 : y1;
                    y[l * H + (kb << 6) + c2] = a;
                }
                if (t == 0) g_tick[tile] = 0;
            }
            __syncthreads();
        } else {
            const int pt = tile - 296;
            if (ty == 0) {
                *(float4*)(p.part + ((contrib * 24 + pt) << 6) + (tx << 2)) = smred[0][0][tx];
                __threadfence();
            }
            __syncthreads();
            if (t == 0) sold = atomicAdd(&g_tick[tile], 1);
            __syncthreads();
            if (sold == 7) {
                __threadfence();
                if (t < 64) {
                    float a = 0.f;
                    #pragma unroll
                    for (int c8 = 0; c8 < 8; ++c8)
                        a += __ldcg(p.part + ((c8 * 24 + pt) << 6) + t);
                    y0[l * H + (kb << 6) + t] = a;
                }
                if (t == 0) g_tick[tile] = 0;
            }
            __syncthreads();
        }
    }
}

// ---------------------------------------------------------------------------
// Final score_mix: h_next = mix(Lzh + Rz2h + b), cand3 = zhtil + z2h + b3.
// ---------------------------------------------------------------------------
__global__ void __launch_bounds__(1024) final_kernel(P p) {
    const int t = threadIdx.x;
    const int lane = t & 31, warp = t >> 5;
    __shared__ float red2[4][32];
    __shared__ float wsh[4];

    if (t < 320) g_tick[t] = 0;   // belt: tickets already self-reset

    float4 ws = ld4(p.Wsc, t);
    float4 cc[4];
    #pragma unroll
    for (int l = 0; l < 3; ++l)
        cc[l] = f4add(f4add(ld4(p.Lzh + l * H, t), ld4(p.Rz2h + l * H, t)), ld4(p.b + l * H, t));
    cc[3] = f4add(f4add(ld4(p.zhtil, t), ld4(p.z2h, t)), ld4(p.b + 3 * H, t));

    #pragma unroll
    for (int l = 0; l < 4; ++l) {
        float v = wred(dot4(cc[l], ws));
        if (lane == 0) red2[l][warp] = v;
    }
    __syncthreads();
    if (warp == 0) {
        float v[4];
        #pragma unroll
        for (int l = 0; l < 4; ++l) {
            v[l] = red2[l][lane];
            #pragma unroll
            for (int off = 16; off > 0; off >>= 1)
                v[l] += __shfl_down_sync(0xffffffffu, v[l], off);
        }
        if (lane == 0) {
            int amax = 0; float m1 = v[0];
            for (int l = 1; l < 4; ++l) if (v[l] > m1) { m1 = v[l]; amax = l; }
            float m2 = -INFINITY;
            for (int l = 0; l < 4; ++l) if (l != amax && v[l] > m2) m2 = v[l];
            float e[4], se = 0.f;
            for (int l = 0; l < 4; ++l) { e[l] = __expf(v[l] - m1); se += e[l]; }
            for (int l = 0; l < 4; ++l) wsh[l] = e[l] / se;
            p.out[4096 + 3 + 5] = (float)amax;
            p.out[4096 + 9 + 5] = m1 - m2;
        }
    }
    __syncthreads();

    float4 o = make_float4(0.f, 0.f, 0.f, 0.f);
    #pragma unroll
    for (int l = 0; l < 4; ++l) o = f4smad(wsh[l], cc[l], o);
    ((float4*)p.out)[t] = o;
}

// ---------------------------------------------------------------------------
// Launch sequence (graph-capturable: kernel launches only, default stream).
// ---------------------------------------------------------------------------
extern "C" void kernel_launch(void* const* d_in, const int* in_sizes, int n_in,
                              void* d_out_v, int out_size) {
    float* S = nullptr;
    cudaGetSymbolAddress((void**)&S, g_scratch);

    P p;
    p.L   = (const float*)d_in[2];
    p.R   = (const float*)d_in[3];
    p.x   = (const float*)d_in[0];
    p.hp  = (const float*)d_in[1];
    p.b   = (const float*)d_in[4];
    p.Wsc = (const float*)d_in[5];
    p.out = (float*)d_out_v;

    p.xL     = S + 0 * H;   p.hL     = S + 3 * H;   p.hR     = S + 6 * H;  // hR: 2H
    p.Rr     = S + 8 * H;   p.Rz1    = S + 11 * H;
    p.Rrh    = S + 14 * H;  p.RoneMZ = S + 17 * H;  p.Rz2h   = S + 20 * H;
    p.Lht    = S + 23 * H;  p.Lzh    = S + 26 * H;
    p.r      = S + 29 * H;  p.z1     = S + 30 * H;  p.rh     = S + 31 * H;
    p.oneMZ  = S + 32 * H;  p.z2h    = S + 33 * H;
    p.htilde = S + 34 * H;  p.zhtil  = S + 35 * H;
    p.part   = S + 36 * H;

    cudaGetSymbolAddress((void**)&p.L16, g_L16);
    cudaGetSymbolAddress((void**)&p.R16, g_R16);

    const int DSM1 = 1 * H * (int)sizeof(float);   // 16KB
    const int DSM2 = 2 * H * (int)sizeof(float);   // 32KB
    const int DSM3 = 3 * H * (int)sizeof(float);   // 48KB
    cudaFuncSetAttribute(fused_kernel<0>, cudaFuncAttributeMaxDynamicSharedMemorySize, DSM2);
    cudaFuncSetAttribute(fused_kernel<1>, cudaFuncAttributeMaxDynamicSharedMemorySize, DSM2);
    cudaFuncSetAttribute(fused_kernel<2>, cudaFuncAttributeMaxDynamicSharedMemorySize, DSM3);
    cudaFuncSetAttribute(fused_kernel<3>, cudaFuncAttributeMaxDynamicSharedMemorySize, DSM1);
    cudaFuncSetAttribute(fused_kernel<4>, cudaFuncAttributeMaxDynamicSharedMemorySize, DSM1);

    dim3 blk(16, 32);

    fused_kernel<0><<<296, blk, DSM2>>>(p);  // A: L x {x,hp} (+L16), R x {hp}   416MB
    fused_kernel<1><<<296, blk, DSM2>>>(p);  // B: glue + R x {r,z1} (+R16)      288MB
    fused_kernel<2><<<296, blk, DSM3>>>(p);  // C: 3-mix + R16 x {rh,oMZ,z2h}     96MB
    fused_kernel<3><<<296, blk, DSM1>>>(p);  // D: h_tilde + L16 x {htilde}       96MB
    fused_kernel<4><<<296, blk, DSM1>>>(p);  // E: zh_tilde + L16 x {zhtil}       96MB
    final_kernel<<<1, 1024>>>(p);            // F: h_next
}

// round 15
// speedup vs baseline: 1.3431x; 1.3431x over previous
#include <cuda_runtime.h>
#include <cuda_fp16.h>
#include <math.h>

#define H 4096

// Finals (36H) + split-tile partials. fp16 weight copies as device globals.
__device__ float g_scratch[47 * H];
__device__ int g_tick[320];               // per-tile tickets, self-resetting
__device__ __half g_L16[3 * H * H];       // 96MB fp16 copy of L l=0..2
__device__ __half g_R16[3 * H * H];       // 96MB fp16 copy of R l=0..2

struct P {
    const float* L; const float* R;
    const float* x; const float* hp;
    const float* b; const float* Wsc;
    float* xL; float* hL; float* hR;          // hR: l=0..1 only
    float* Rr; float* Rz1;
    float* Rrh; float* RoneMZ; float* Rz2h;
    float* Lht; float* Lzh;
    float* r; float* z1; float* rh; float* oneMZ; float* z2h;
    float* htilde; float* zhtil;
    float* part;
    __half* L16; __half* R16;
    float* out;
};

// ---------------- helpers ----------------
__device__ __forceinline__ float4 f4add(float4 a, float4 b) {
    return make_float4(a.x + b.x, a.y + b.y, a.z + b.z, a.w + b.w);
}
__device__ __forceinline__ float4 f4fma(float4 a, float4 b, float4 c) {
    return make_float4(a.x * b.x + c.x, a.y * b.y + c.y, a.z * b.z + c.z, a.w * b.w + c.w);
}
__device__ __forceinline__ float4 f4smad(float s, float4 a, float4 acc) {
    return make_float4(s * a.x + acc.x, s * a.y + acc.y, s * a.z + acc.z, s * a.w + acc.w);
}
__device__ __forceinline__ float4 f4rsub1(float4 a) {
    return make_float4(1.f - a.x, 1.f - a.y, 1.f - a.z, 1.f - a.w);
}
__device__ __forceinline__ float ftanh(float x) { return 1.f - 2.f / (1.f + __expf(2.f * x)); }
__device__ __forceinline__ float fsig(float x)  { return 1.f / (1.f + __expf(-x)); }
__device__ __forceinline__ float4 f4tanh(float4 a) {
    return make_float4(ftanh(a.x), ftanh(a.y), ftanh(a.z), ftanh(a.w));
}
__device__ __forceinline__ float4 f4sig(float4 a) {
    return make_float4(fsig(a.x), fsig(a.y), fsig(a.z), fsig(a.w));
}
__device__ __forceinline__ float dot4(float4 a, float4 b) {
    return a.x * b.x + a.y * b.y + a.z * b.z + a.w * b.w;
}
__device__ __forceinline__ float4 ld4(const float* p, int i) {
    return __ldg(((const float4*)p) + i);
}
__device__ __forceinline__ float wred(float v) {
    v += __shfl_down_sync(0xffffffffu, v, 16);
    v += __shfl_down_sync(0xffffffffu, v, 8);
    v += __shfl_down_sync(0xffffffffu, v, 4);
    v += __shfl_down_sync(0xffffffffu, v, 2);
    v += __shfl_down_sync(0xffffffffu, v, 1);
    return v;
}

// Candidate values for the score_mix fused into stage MODE (2,3,4).
template<int MODE>
__device__ __forceinline__ void cands(const P& p, int idx, int l, float4* cc) {
    float4 b_ = ld4(p.b + l * H, idx);
    if (MODE == 2) {
        if (l < 3) {
            float4 hl = ld4(p.hL + l * H, idx);
            float4 rr = ld4(p.Rr + l * H, idx);
            float4 rz = ld4(p.Rz1 + l * H, idx);
            cc[0] = f4fma(hl, rr, b_);
            cc[1] = f4rsub1(f4add(rz, b_));
            cc[2] = f4fma(hl, rz, b_);
        } else {
            float4 hp4 = ld4(p.hp, idx);
            float4 r4  = ld4(p.r, idx);
            float4 z4  = ld4(p.z1, idx);
            cc[0] = f4fma(hp4, r4, b_);
            cc[1] = f4rsub1(f4add(z4, b_));
            cc[2] = f4fma(hp4, z4, b_);
        }
    } else if (MODE == 3) {
        if (l < 3)
            cc[0] = f4tanh(f4add(f4add(ld4(p.xL + l * H, idx), ld4(p.Rrh + l * H, idx)), b_));
        else
            cc[0] = f4tanh(f4add(f4add(ld4(p.x, idx), ld4(p.rh, idx)), b_));
    } else {  // MODE == 4
        if (l < 3)
            cc[0] = f4fma(ld4(p.Lht + l * H, idx), ld4(p.RoneMZ + l * H, idx), b_);
        else
            cc[0] = f4fma(ld4(p.htilde, idx), ld4(p.oneMZ, idx), b_);
    }
}

// fp32 streaming matvec (R4/R10-proven pattern).
template<int NVST, int RPT>
__device__ __forceinline__ void run_mv(const float* __restrict__ Wp,
                                       const float* v0s, const float* v1s, const float* v2s,
                                       int nv, float4& a0, float4& a1, float4& a2) {
    float4 x0 = make_float4(0.f, 0.f, 0.f, 0.f), x1 = x0, x2 = x0;
    if (NVST == 1 || nv == 1) {
        #pragma unroll 8
        for (int h = 0; h < RPT; ++h) {
            float4 w = __ldg((const float4*)(Wp + (size_t)h * H));
            x0 = f4smad(v0s[h], w, x0);
        }
    } else if (nv == 2) {
        #pragma unroll 4
        for (int h = 0; h < RPT; ++h) {
            float4 w = __ldg((const float4*)(Wp + (size_t)h * H));
            float s0 = v0s[h], s1 = v1s[h];
            x0 = f4smad(s0, w, x0);
            x1 = f4smad(s1, w, x1);
        }
    } else {
        #pragma unroll 4
        for (int h = 0; h < RPT; ++h) {
            float4 w = __ldg((const float4*)(Wp + (size_t)h * H));
            float s0 = v0s[h], s1 = v1s[h], s2 = v2s[h];
            x0 = f4smad(s0, w, x0);
            x1 = f4smad(s1, w, x1);
            x2 = f4smad(s2, w, x2);
        }
    }
    a0 = x0; a1 = x1; a2 = x2;
}

// fp32 matvec (nv=2) + on-the-fly fp16 conversion store.
template<int RPT>
__device__ __forceinline__ void run_mv_conv(const float* __restrict__ Wp, __half* O16,
                                            const float* v0s, const float* v1s,
                                            float4& a0, float4& a1) {
    float4 x0 = make_float4(0.f, 0.f, 0.f, 0.f), x1 = x0;
    #pragma unroll 4
    for (int h = 0; h < RPT; ++h) {
        float4 w = __ldg((const float4*)(Wp + (size_t)h * H));
        __half2 h01 = __floats2half2_rn(w.x, w.y);
        __half2 h23 = __floats2half2_rn(w.z, w.w);
        uint2 u;
        u.x = *reinterpret_cast<unsigned*>(&h01);
        u.y = *reinterpret_cast<unsigned*>(&h23);
        *reinterpret_cast<uint2*>(O16 + (size_t)h * H) = u;
        float s0 = v0s[h], s1 = v1s[h];
        x0 = f4smad(s0, w, x0);
        x1 = f4smad(s1, w, x1);
    }
    a0 = x0; a1 = x1;
}

// fp16-weight streaming matvec: 16B loads. nv=1 uses unroll 8 (8 LDG.128 in
// flight = 128B/thread, matching the proven fp32 config); nv=3 keeps unroll 4
// (register budget).
template<int NVST, int RPT>
__device__ __forceinline__ void run_mv_f16w(const __half* __restrict__ Wp,
                                            const float* v0s, const float* v1s, const float* v2s,
                                            int nv, float a[NVST][8]) {
    #pragma unroll
    for (int j = 0; j < NVST; ++j)
        #pragma unroll
        for (int f = 0; f < 8; ++f) a[j][f] = 0.f;
    if (NVST == 1) {
        #pragma unroll 8
        for (int h = 0; h < RPT; ++h) {
            uint4 raw = __ldg((const uint4*)(Wp + (size_t)h * H));
            float2 f0 = __half22float2(*reinterpret_cast<__half2*>(&raw.x));
            float2 f1 = __half22float2(*reinterpret_cast<__half2*>(&raw.y));
            float2 f2 = __half22float2(*reinterpret_cast<__half2*>(&raw.z));
            float2 f3 = __half22float2(*reinterpret_cast<__half2*>(&raw.w));
            float wv[8] = {f0.x, f0.y, f1.x, f1.y, f2.x, f2.y, f3.x, f3.y};
            float s0 = v0s[h];
            #pragma unroll
            for (int f = 0; f < 8; ++f) a[0][f] += s0 * wv[f];
        }
    } else {
        #pragma unroll 4
        for (int h = 0; h < RPT; ++h) {
            uint4 raw = __ldg((const uint4*)(Wp + (size_t)h * H));
            float2 f0 = __half22float2(*reinterpret_cast<__half2*>(&raw.x));
            float2 f1 = __half22float2(*reinterpret_cast<__half2*>(&raw.y));
            float2 f2 = __half22float2(*reinterpret_cast<__half2*>(&raw.z));
            float2 f3 = __half22float2(*reinterpret_cast<__half2*>(&raw.w));
            float wv[8] = {f0.x, f0.y, f1.x, f1.y, f2.x, f2.y, f3.x, f3.y};
            float s0 = v0s[h];
            #pragma unroll
            for (int f = 0; f < 8; ++f) a[0][f] += s0 * wv[f];
            if (NVST > 1 && nv > 1) {
                float s1 = v1s[h];
                #pragma unroll
                for (int f = 0; f < 8; ++f) a[1][f] += s1 * wv[f];
            }
            if (NVST > 2 && nv > 2) {
                float s2 = v2s[h];
                #pragma unroll
                for (int f = 0; f < 8; ++f) a[2][f] += s2 * wv[f];
            }
        }
    }
}

// ---------------------------------------------------------------------------
// Fused kernel (R13 structure): [prologue -> vsm] + static pair-aware split
// streaming matvec. A converts L->fp16; B converts R->fp16; C/D/E stream
// fp16 weights with 16B loads ((8,64) thread indexing, intra-warp shuffle +
// 16-way fixed-order tree reduction). Split tiles combine via tickets.
// ---------------------------------------------------------------------------
template<int MODE>
__global__ void __launch_bounds__(512, 2) fused_kernel(P p) {
    extern __shared__ float vsm[];                 // [NVST][H] input vectors
    constexpr int NVST = (MODE == 2) ? 3 : ((MODE == 3 || MODE == 4) ? 1 : 2);
    __shared__ float4 smred[2][32][16];            // fp32 modes (NVST<=2 there)
    __shared__ float sm16[16][8][NVST * 8];        // fp16 modes
    __shared__ float red[12][16];
    __shared__ float wsm[3][4];
    __shared__ int sold;

    const int tx = threadIdx.x, ty = threadIdx.y;  // 16 x 32
    const int t = ty * 16 + tx;
    const int lane = t & 31, warp = t >> 5;
    const int bx = blockIdx.x;

    // ---------------- prologue: fill vsm ----------------
    if (MODE == 0) {
        #pragma unroll
        for (int c = 0; c < 2; ++c) {
            int idx = t + c * 512;
            ((float4*)vsm)[idx]       = ld4(p.x, idx);
            ((float4*)(vsm + H))[idx] = ld4(p.hp, idx);
        }
        __syncthreads();
    } else if (MODE == 1) {
        #pragma unroll
        for (int c = 0; c < 2; ++c) {
            int idx = t + c * 512;
            float4 z14 = f4sig(f4add(f4add(ld4(p.xL, idx),     ld4(p.hR, idx)),     ld4(p.b, idx)));
            float4 r4  = f4sig(f4add(f4add(ld4(p.xL + H, idx), ld4(p.hR + H, idx)), ld4(p.b + H, idx)));
            ((float4*)vsm)[idx]       = r4;    // v0 = r
            ((float4*)(vsm + H))[idx] = z14;   // v1 = z1
            if (bx == 0) {
                ((float4*)p.r)[idx]  = r4;
                ((float4*)p.z1)[idx] = z14;
            }
        }
        if (bx == 0 && t < 3) p.out[4096 + t] = (t == 1) ? 1.f : 0.f;
        __syncthreads();
    } else {
        constexpr int NM = (MODE == 2) ? 3 : 1;
        float s[NM * 4];
        #pragma unroll
        for (int d = 0; d < NM * 4; ++d) s[d] = 0.f;

        #pragma unroll
        for (int c = 0; c < 2; ++c) {
            int idx = t + c * 512;
            float4 ws = ld4(p.Wsc, idx);
            #pragma unroll
            for (int ll = 0; ll < 4; ++ll) {
                float4 cc[NM];
                cands<MODE>(p, idx, ll, cc);
                #pragma unroll
                for (int m = 0; m < NM; ++m) s[m * 4 + ll] += dot4(cc[m], ws);
            }
        }
        #pragma unroll
        for (int d = 0; d < NM * 4; ++d) {
            float v = wred(s[d]);
            if (lane == 0) red[d][warp] = v;
        }
        __syncthreads();
        if (t == 0) {
            #pragma unroll
            for (int m = 0; m < NM; ++m) {
                float sc[4];
                #pragma unroll
                for (int l2 = 0; l2 < 4; ++l2) {
                    float a = 0.f;
                    #pragma unroll
                    for (int w2 = 0; w2 < 16; ++w2) a += red[m * 4 + l2][w2];
                    sc[l2] = a;
                }
                int amax = 0; float m1 = sc[0];
                for (int l2 = 1; l2 < 4; ++l2) if (sc[l2] > m1) { m1 = sc[l2]; amax = l2; }
                float m2 = -INFINITY;
                for (int l2 = 0; l2 < 4; ++l2) if (l2 != amax && sc[l2] > m2) m2 = sc[l2];
                float e[4], se = 0.f;
                for (int l2 = 0; l2 < 4; ++l2) { e[l2] = __expf(sc[l2] - m1); se += e[l2]; }
                for (int l2 = 0; l2 < 4; ++l2) wsm[m][l2] = e[l2] / se;
                if (bx == 0) {
                    int slot = (MODE == 2) ? (m * 2) : ((MODE == 3) ? 1 : 3);
                    p.out[4096 + 3 + slot] = (float)amax;
                    p.out[4096 + 9 + slot] = m1 - m2;
                }
            }
        }
        __syncthreads();

        float* gv[NM];
        if (MODE == 2) { gv[0] = p.rh; gv[1] = p.oneMZ; gv[2] = p.z2h; }
        if (MODE == 3) { gv[0] = p.htilde; }
        if (MODE == 4) { gv[0] = p.zhtil; }
        #pragma unroll
        for (int c = 0; c < 2; ++c) {
            int idx = t + c * 512;
            float4 v[NM];
            #pragma unroll
            for (int m = 0; m < NM; ++m) v[m] = make_float4(0.f, 0.f, 0.f, 0.f);
            #pragma unroll
            for (int ll = 0; ll < 4; ++ll) {
                float4 cc[NM];
                cands<MODE>(p, idx, ll, cc);
                #pragma unroll
                for (int m = 0; m < NM; ++m) v[m] = f4smad(wsm[m][ll], cc[m], v[m]);
            }
            #pragma unroll
            for (int m = 0; m < NM; ++m) {
                ((float4*)(vsm + m * H))[idx] = v[m];
                if (bx == 0) ((float4*)gv[m])[idx] = v[m];
            }
        }
        __syncthreads();
    }

    // ---------------- decode (R10 static pair-aware split) ----------------
    for (int seg = 0; seg < 2; ++seg) {
        int tile, rowbase, half, contrib;
        if (seg == 0) {
            if (MODE == 0)            { tile = bx;        rowbase = 0;    half = 0; contrib = -1; }
            else if (bx < 104)        { tile = bx;        rowbase = 0;    half = 1; contrib = 0; }
            else if (bx < 192)        { tile = bx;        rowbase = 0;    half = 0; contrib = -1; }
            else                      { tile = bx - 192;  rowbase = 2048; half = 1; contrib = 1; }
        } else {
            if (MODE != 0 || bx >= 192) break;
            tile = 296 + (bx >> 3); rowbase = (bx & 7) * 512; half = 2; contrib = bx & 7;
        }

        const int unit = tile >> 6;
        const int kb = tile & 63;
        int l, nv;
        float *y0 = nullptr, *y1 = nullptr, *y2 = nullptr;
        const float *v0 = vsm, *v1 = vsm + H, *v2 = vsm + 2 * H;
        if (MODE == 0) {
            if (unit < 3) { l = unit;     nv = 2; y0 = p.xL; y1 = p.hL; }
            else          { l = unit - 3; nv = 1; y0 = p.hR; v0 = vsm + H; }
        } else {
            l = unit;
            nv = (MODE == 2) ? 3 : ((MODE == 1) ? 2 : 1);
            if (MODE == 1) { y0 = p.Rr;  y1 = p.Rz1; }
            if (MODE == 2) { y0 = p.Rrh; y1 = p.RoneMZ; y2 = p.Rz2h; }
            if (MODE == 3) { y0 = p.Lht; }
            if (MODE == 4) { y0 = p.Lzh; }
        }

        if (MODE >= 2) {
            // ---------- fp16 path: (8,64) indexing, 16B loads ----------
            const int tx8 = t & 7, ty64 = t >> 3;
            const int k0 = (kb << 6) + (tx8 << 3);
            const int rpt = half ? 32 : 64;
            const int h0 = rowbase + ty64 * rpt;
            const __half* W16 = ((MODE == 2) ? p.R16 : p.L16)
                                + (size_t)l * H * H + (size_t)h0 * H + k0;
            float a[NVST][8];
            if (half) run_mv_f16w<NVST, 32>(W16, v0 + h0, v1 + h0, v2 + h0, nv, a);
            else      run_mv_f16w<NVST, 64>(W16, v0 + h0, v1 + h0, v2 + h0, nv, a);

            // intra-warp: combine the 4 ty-slices (lane>>3) per warp
            #pragma unroll
            for (int j = 0; j < NVST; ++j)
                #pragma unroll
                for (int f = 0; f < 8; ++f) {
                    float v = a[j][f];
                    v += __shfl_down_sync(0xffffffffu, v, 16);
                    v += __shfl_down_sync(0xffffffffu, v, 8);
                    a[j][f] = v;
                }
            if (lane < 8) {
                #pragma unroll
                for (int j = 0; j < NVST; ++j)
                    #pragma unroll
                    for (int f = 0; f < 8; ++f)
                        sm16[warp][lane][j * 8 + f] = a[j][f];
            }
            __syncthreads();

            // 16-way fixed-order tree + output
            const int nel = nv * 64;
            float accv = 0.f; int ej = 0, ec = 0;
            if (t < nel) {
                ej = t >> 6; ec = t & 63;
                const int txe = ec >> 3, fe = ec & 7;
                #pragma unroll
                for (int w2 = 0; w2 < 16; ++w2) accv += sm16[w2][txe][ej * 8 + fe];
            }
            if (contrib < 0) {
                if (t < nel) {
                    float* y = (ej == 0) ? y0 : ((ej == 1) ? y1 : y2);
                    y[l * H + (kb << 6) + ec] = accv;
                }
            } else {
                if (t < nel) {
                    p.part[(((contrib * 3 + ej) * 104 + tile) << 6) + ec] = accv;
                    __threadfence();
                }
                __syncthreads();
                if (t == 0) sold = atomicAdd(&g_tick[tile], 1);
                __syncthreads();
                if (sold == 1) {
                    __threadfence();
                    if (t < nel) {
                        float aa = __ldcg(p.part + (((0 * 3 + ej) * 104 + tile) << 6) + ec)
                                 + __ldcg(p.part + (((1 * 3 + ej) * 104 + tile) << 6) + ec);
                        float* y = (ej == 0) ? y0 : ((ej == 1) ? y1 : y2);
                        y[l * H + (kb << 6) + ec] = aa;
                    }
                    if (t == 0) g_tick[tile] = 0;
                }
            }
            __syncthreads();
            continue;
        }

        // ---------- fp32 path (MODE 0/1), R13 code ----------
        const int k0 = (kb << 6) + (tx << 2);
        const int rpt = (half == 0) ? 128 : ((half == 1) ? 64 : 16);
        const int h0 = rowbase + ty * rpt;
        float4 a0 = make_float4(0.f, 0.f, 0.f, 0.f), a1 = a0, a2 = a0;

        if (MODE == 0) {
            const float* W = (unit < 3) ? p.L : p.R;
            const float* Wp = W + (size_t)l * H * H + (size_t)h0 * H + k0;
            if (unit < 3) {
                __half* O16 = p.L16 + (size_t)l * H * H + (size_t)h0 * H + k0;
                run_mv_conv<128>(Wp, O16, v0 + h0, v1 + h0, a0, a1);
            } else if (half == 0) {
                run_mv<2, 128>(Wp, v0 + h0, v1 + h0, v2 + h0, 1, a0, a1, a2);
            } else {
                run_mv<2, 16>(Wp, v0 + h0, v1 + h0, v2 + h0, 1, a0, a1, a2);
            }
        } else {
            const float* Wp = p.R + (size_t)l * H * H + (size_t)h0 * H + k0;
            __half* O16 = p.R16 + (size_t)l * H * H + (size_t)h0 * H + k0;
            if (half == 0) run_mv_conv<128>(Wp, O16, v0 + h0, v1 + h0, a0, a1);
            else           run_mv_conv<64>(Wp, O16, v0 + h0, v1 + h0, a0, a1);
        }

        if (seg == 1) __syncthreads();
        smred[0][ty][tx] = a0;
        if (nv > 1) smred[1][ty][tx] = a1;
        __syncthreads();

        #pragma unroll
        for (int s = 16; s > 0; s >>= 1) {
            if (ty < s) {
                #pragma unroll
                for (int vv = 0; vv < 2; ++vv)
                    if (vv < nv)
                        smred[vv][ty][tx] = f4add(smred[vv][ty][tx], smred[vv][ty + s][tx]);
            }
            __syncthreads();
        }

        if (contrib < 0) {
            if (ty == 0) {
                *(float4*)(y0 + l * H + k0) = smred[0][0][tx];
                if (nv > 1) *(float4*)(y1 + l * H + k0) = smred[1][0][tx];
            }
        } else if (MODE != 0) {
            if (ty == 0) {
                #pragma unroll
                for (int j = 0; j < 2; ++j)
                    if (j < nv)
                        *(float4*)(p.part + (((contrib * 3 + j) * 104 + tile) << 6) + (tx << 2))
                            = smred[j][0][tx];
                __threadfence();
            }
            __syncthreads();
            if (t == 0) sold = atomicAdd(&g_tick[tile], 1);
            __syncthreads();
            if (sold == 1) {
                __threadfence();
                if (t < 64 * nv) {
                    const int j = t >> 6, c2 = t & 63;
                    float a = __ldcg(p.part + (((0 * 3 + j) * 104 + tile) << 6) + c2)
                            + __ldcg(p.part + (((1 * 3 + j) * 104 + tile) << 6) + c2);
                    float* y = (j == 0) ? y0 : y1;
                    y[l * H + (kb << 6) + c2] = a;
                }
                if (t == 0) g_tick[tile] = 0;
            }
            __syncthreads();
        } else {
            const int pt = tile - 296;
            if (ty == 0) {
                *(float4*)(p.part + ((contrib * 24 + pt) << 6) + (tx << 2)) = smred[0][0][tx];
                __threadfence();
            }
            __syncthreads();
            if (t == 0) sold = atomicAdd(&g_tick[tile], 1);
            __syncthreads();
            if (sold == 7) {
                __threadfence();
                if (t < 64) {
                    float a = 0.f;
                    #pragma unroll
                    for (int c8 = 0; c8 < 8; ++c8)
                        a += __ldcg(p.part + ((c8 * 24 + pt) << 6) + t);
                    y0[l * H + (kb << 6) + t] = a;
                }
                if (t == 0) g_tick[tile] = 0;
            }
            __syncthreads();
        }
    }
}

// ---------------------------------------------------------------------------
// Final score_mix: h_next = mix(Lzh + Rz2h + b), cand3 = zhtil + z2h + b3.
// ---------------------------------------------------------------------------
__global__ void __launch_bounds__(1024) final_kernel(P p) {
    const int t = threadIdx.x;
    const int lane = t & 31, warp = t >> 5;
    __shared__ float red2[4][32];
    __shared__ float wsh[4];

    if (t < 320) g_tick[t] = 0;   // belt: tickets already self-reset

    float4 ws = ld4(p.Wsc, t);
    float4 cc[4];
    #pragma unroll
    for (int l = 0; l < 3; ++l)
        cc[l] = f4add(f4add(ld4(p.Lzh + l * H, t), ld4(p.Rz2h + l * H, t)), ld4(p.b + l * H, t));
    cc[3] = f4add(f4add(ld4(p.zhtil, t), ld4(p.z2h, t)), ld4(p.b + 3 * H, t));

    #pragma unroll
    for (int l = 0; l < 4; ++l) {
        float v = wred(dot4(cc[l], ws));
        if (lane == 0) red2[l][warp] = v;
    }
    __syncthreads();
    if (warp == 0) {
        float v[4];
        #pragma unroll
        for (int l = 0; l < 4; ++l) {
            v[l] = red2[l][lane];
            #pragma unroll
            for (int off = 16; off > 0; off >>= 1)
                v[l] += __shfl_down_sync(0xffffffffu, v[l], off);
        }
        if (lane == 0) {
            int amax = 0; float m1 = v[0];
            for (int l = 1; l < 4; ++l) if (v[l] > m1) { m1 = v[l]; amax = l; }
            float m2 = -INFINITY;
            for (int l = 0; l < 4; ++l) if (l != amax && v[l] > m2) m2 = v[l];
            float e[4], se = 0.f;
            for (int l = 0; l < 4; ++l) { e[l] = __expf(v[l] - m1); se += e[l]; }
            for (int l = 0; l < 4; ++l) wsh[l] = e[l] / se;
            p.out[4096 + 3 + 5] = (float)amax;
            p.out[4096 + 9 + 5] = m1 - m2;
        }
    }
    __syncthreads();

    float4 o = make_float4(0.f, 0.f, 0.f, 0.f);
    #pragma unroll
    for (int l = 0; l < 4; ++l) o = f4smad(wsh[l], cc[l], o);
    ((float4*)p.out)[t] = o;
}

// ---------------------------------------------------------------------------
// Launch sequence (graph-capturable: kernel launches only, default stream).
// ---------------------------------------------------------------------------
extern "C" void kernel_launch(void* const* d_in, const int* in_sizes, int n_in,
                              void* d_out_v, int out_size) {
    float* S = nullptr;
    cudaGetSymbolAddress((void**)&S, g_scratch);

    P p;
    p.L   = (const float*)d_in[2];
    p.R   = (const float*)d_in[3];
    p.x   = (const float*)d_in[0];
    p.hp  = (const float*)d_in[1];
    p.b   = (const float*)d_in[4];
    p.Wsc = (const float*)d_in[5];
    p.out = (float*)d_out_v;

    p.xL     = S + 0 * H;   p.hL     = S + 3 * H;   p.hR     = S + 6 * H;  // hR: 2H
    p.Rr     = S + 8 * H;   p.Rz1    = S + 11 * H;
    p.Rrh    = S + 14 * H;  p.RoneMZ = S + 17 * H;  p.Rz2h   = S + 20 * H;
    p.Lht    = S + 23 * H;  p.Lzh    = S + 26 * H;
    p.r      = S + 29 * H;  p.z1     = S + 30 * H;  p.rh     = S + 31 * H;
    p.oneMZ  = S + 32 * H;  p.z2h    = S + 33 * H;
    p.htilde = S + 34 * H;  p.zhtil  = S + 35 * H;
    p.part   = S + 36 * H;

    cudaGetSymbolAddress((void**)&p.L16, g_L16);
    cudaGetSymbolAddress((void**)&p.R16, g_R16);

    const int DSM1 = 1 * H * (int)sizeof(float);   // 16KB
    const int DSM2 = 2 * H * (int)sizeof(float);   // 32KB
    const int DSM3 = 3 * H * (int)sizeof(float);   // 48KB
    cudaFuncSetAttribute(fused_kernel<0>, cudaFuncAttributeMaxDynamicSharedMemorySize, DSM2);
    cudaFuncSetAttribute(fused_kernel<1>, cudaFuncAttributeMaxDynamicSharedMemorySize, DSM2);
    cudaFuncSetAttribute(fused_kernel<2>, cudaFuncAttributeMaxDynamicSharedMemorySize, DSM3);
    cudaFuncSetAttribute(fused_kernel<3>, cudaFuncAttributeMaxDynamicSharedMemorySize, DSM1);
    cudaFuncSetAttribute(fused_kernel<4>, cudaFuncAttributeMaxDynamicSharedMemorySize, DSM1);

    dim3 blk(16, 32);

    fused_kernel<0><<<296, blk, DSM2>>>(p);  // A: L x {x,hp} (+L16), R x {hp}   416MB
    fused_kernel<1><<<296, blk, DSM2>>>(p);  // B: glue + R x {r,z1} (+R16)      288MB
    fused_kernel<2><<<296, blk, DSM3>>>(p);  // C: 3-mix + R16 x {rh,oMZ,z2h}     96MB
    fused_kernel<3><<<296, blk, DSM1>>>(p);  // D: h_tilde + L16 x {htilde}       96MB
    fused_kernel<4><<<296, blk, DSM1>>>(p);  // E: zh_tilde + L16 x {zhtil}       96MB
    final_kernel<<<1, 1024>>>(p);            // F: h_next
}